// round 1
// baseline (speedup 1.0000x reference)
#include <cuda_runtime.h>

#define NS   1024
#define XD   128
#define HID  256

// Scratch (device globals — no allocation allowed)
__device__ float g_px_t[HID * NS];   // pre_x transposed: [k][j]
__device__ float g_py_t[HID * NS];   // (pre_y + b1) transposed: [k][i]
__device__ float g_sum_exp;
__device__ float g_sum_diag;

// ---------------------------------------------------------------------------
// Kernel 1: pre_x = x @ W1[:128], pre_yb = y @ W1[128:] + b1, stored transposed.
// grid (HID/64, NS/64, 2), block (16,16). Tile 64(rows n) x 64(cols hid), 4x4 micro.
// ---------------------------------------------------------------------------
__global__ void gemm_pre_kernel(const float* __restrict__ x,
                                const float* __restrict__ y,
                                const float* __restrict__ W1,
                                const float* __restrict__ b1) {
    const int bz = blockIdx.z;
    const float* __restrict__ A = bz ? y : x;
    const float* __restrict__ W = W1 + (bz ? (XD * HID) : 0);
    float* __restrict__ outT = bz ? g_py_t : g_px_t;

    __shared__ float As[16][64];   // [k][n]
    __shared__ float Bs[16][64];   // [k][h]

    const int tx = threadIdx.x, ty = threadIdx.y;
    const int tid = ty * 16 + tx;
    const int n0 = blockIdx.y * 64;
    const int h0 = blockIdx.x * 64;

    float acc[4][4];
#pragma unroll
    for (int a = 0; a < 4; a++)
#pragma unroll
        for (int b = 0; b < 4; b++) acc[a][b] = 0.0f;

    for (int kk = 0; kk < XD; kk += 16) {
        // Load A tile: 64 rows x 16 k. One float4 per thread (256 float4 total).
        {
            int m  = tid >> 2;            // 0..63
            int k4 = (tid & 3) * 4;       // 0,4,8,12
            float4 v = *(const float4*)&A[(n0 + m) * XD + kk + k4];
            As[k4 + 0][m] = v.x;
            As[k4 + 1][m] = v.y;
            As[k4 + 2][m] = v.z;
            As[k4 + 3][m] = v.w;
        }
        // Load W tile: 16 k x 64 hid. 4 elements per thread, coalesced.
        {
#pragma unroll
            for (int t = 0; t < 4; t++) {
                int e = tid + t * 256;    // 0..1023
                int h = e & 63;
                int k = e >> 6;           // 0..15
                Bs[k][h] = W[(kk + k) * HID + h0 + h];
            }
        }
        __syncthreads();

#pragma unroll
        for (int k = 0; k < 16; k++) {
            float4 av = *(const float4*)&As[k][ty * 4];
            float4 bv = *(const float4*)&Bs[k][tx * 4];
            float aa[4] = {av.x, av.y, av.z, av.w};
            float bb[4] = {bv.x, bv.y, bv.z, bv.w};
#pragma unroll
            for (int a = 0; a < 4; a++)
#pragma unroll
                for (int b = 0; b < 4; b++)
                    acc[a][b] = fmaf(aa[a], bb[b], acc[a][b]);
        }
        __syncthreads();
    }

    // Store transposed: outT[h][n], float4 along n.
#pragma unroll
    for (int b = 0; b < 4; b++) {
        int h = h0 + tx * 4 + b;
        float bias = bz ? b1[h] : 0.0f;
        float4 v = make_float4(acc[0][b] + bias, acc[1][b] + bias,
                               acc[2][b] + bias, acc[3][b] + bias);
        *(float4*)&outT[h * NS + n0 + ty * 4] = v;
    }
}

// ---------------------------------------------------------------------------
// Kernel 2: fused pairwise T1 + exp-sum + diagonal-sum.
// grid (16,16), block (16,16). Tile: 64 i x 64 j, 4x4 micro, k-chunks of 32.
// ---------------------------------------------------------------------------
__global__ void __launch_bounds__(256, 4)
pairwise_kernel(const float* __restrict__ W2, const float* __restrict__ b2) {
    __shared__ float Ys[32][64];     // [k][i_local]
    __shared__ float Xs[32][64];     // [k][j_local]
    __shared__ float w2s[HID];
    __shared__ float r1[8], r2[8];

    const int tx = threadIdx.x, ty = threadIdx.y;
    const int tid = ty * 16 + tx;
    const int bi = blockIdx.y * 64;
    const int bj = blockIdx.x * 64;

    if (tid < HID) w2s[tid] = W2[tid];  // 256 threads == HID

    float acc[4][4];
#pragma unroll
    for (int a = 0; a < 4; a++)
#pragma unroll
        for (int b = 0; b < 4; b++) acc[a][b] = 0.0f;

    for (int kk = 0; kk < HID; kk += 32) {
        // Load 2 float4 per thread per tile (512 float4 each = 32x64 floats).
#pragma unroll
        for (int t = 0; t < 2; t++) {
            int f  = tid + t * 256;       // 0..511
            int kr = f >> 4;              // 0..31
            int c4 = (f & 15) * 4;        // 0..60
            *(float4*)&Ys[kr][c4] = *(const float4*)&g_py_t[(kk + kr) * NS + bi + c4];
            *(float4*)&Xs[kr][c4] = *(const float4*)&g_px_t[(kk + kr) * NS + bj + c4];
        }
        __syncthreads();

#pragma unroll 8
        for (int k = 0; k < 32; k++) {
            float4 yv = *(const float4*)&Ys[k][ty * 4];
            float4 xv = *(const float4*)&Xs[k][tx * 4];
            float w = w2s[kk + k];
            float ya[4] = {yv.x, yv.y, yv.z, yv.w};
            float xb[4] = {xv.x, xv.y, xv.z, xv.w};
#pragma unroll
            for (int a = 0; a < 4; a++)
#pragma unroll
                for (int b = 0; b < 4; b++)
                    acc[a][b] = fmaf(fmaxf(ya[a] + xb[b], 0.0f), w, acc[a][b]);
        }
        __syncthreads();
    }

    const float c = b2[0] - 1.0f;
    float sexp = 0.0f, sdiag = 0.0f;
#pragma unroll
    for (int a = 0; a < 4; a++)
#pragma unroll
        for (int b = 0; b < 4; b++)
            sexp += __expf(acc[a][b] + c);

    if (bi == bj && tx == ty) {
#pragma unroll
        for (int a = 0; a < 4; a++) sdiag += acc[a][a] + c;
    }

    // Block reduction: warp shuffle, then smem across 8 warps.
    const int lane = tid & 31;
    const int wid  = tid >> 5;
#pragma unroll
    for (int o = 16; o > 0; o >>= 1) {
        sexp  += __shfl_down_sync(0xFFFFFFFFu, sexp,  o);
        sdiag += __shfl_down_sync(0xFFFFFFFFu, sdiag, o);
    }
    if (lane == 0) { r1[wid] = sexp; r2[wid] = sdiag; }
    __syncthreads();
    if (tid == 0) {
        float s1 = 0.0f, s2 = 0.0f;
#pragma unroll
        for (int w = 0; w < 8; w++) { s1 += r1[w]; s2 += r2[w]; }
        atomicAdd(&g_sum_exp,  s1);
        atomicAdd(&g_sum_diag, s2);
    }
}

// ---------------------------------------------------------------------------
__global__ void zero_kernel() {
    g_sum_exp = 0.0f;
    g_sum_diag = 0.0f;
}

__global__ void finalize_kernel(float* __restrict__ out) {
    float n = (float)NS;
    out[0] = (g_sum_diag + n) / n - g_sum_exp / (n * n);
}

// ---------------------------------------------------------------------------
extern "C" void kernel_launch(void* const* d_in, const int* in_sizes, int n_in,
                              void* d_out, int out_size) {
    const float* x  = (const float*)d_in[0];
    const float* y  = (const float*)d_in[1];
    const float* W1 = (const float*)d_in[2];
    const float* b1 = (const float*)d_in[3];
    const float* W2 = (const float*)d_in[4];
    const float* b2 = (const float*)d_in[5];
    float* out = (float*)d_out;

    zero_kernel<<<1, 1>>>();

    dim3 blk(16, 16);
    dim3 g1(HID / 64, NS / 64, 2);
    gemm_pre_kernel<<<g1, blk>>>(x, y, W1, b1);

    dim3 g2(NS / 64, NS / 64);
    pairwise_kernel<<<g2, blk>>>(W2, b2);

    finalize_kernel<<<1, 1>>>(out);
}

// round 2
// speedup vs baseline: 1.0430x; 1.0430x over previous
#include <cuda_runtime.h>

#define NS   1024
#define XD   128
#define HID  256

typedef unsigned long long u64;

union F2 { u64 u; float f[2]; };

// Scratch (device globals — no allocation allowed)
__device__ float g_px_t[HID * NS];   // pre_x transposed: [k][j]
__device__ float g_py_t[HID * NS];   // (pre_y + b1) transposed: [k][i]
__device__ float g_sum_exp;
__device__ float g_sum_diag;
__device__ unsigned g_done;

__device__ __forceinline__ u64 pack2(float lo, float hi) {
    u64 r; asm("mov.b64 %0, {%1, %2};" : "=l"(r) : "f"(lo), "f"(hi)); return r;
}
__device__ __forceinline__ u64 add2(u64 a, u64 b) {
    u64 r; asm("add.rn.f32x2 %0, %1, %2;" : "=l"(r) : "l"(a), "l"(b)); return r;
}
__device__ __forceinline__ u64 fma2(u64 a, u64 b, u64 c) {
    u64 r; asm("fma.rn.f32x2 %0, %1, %2, %3;" : "=l"(r) : "l"(a), "l"(b), "l"(c)); return r;
}
__device__ __forceinline__ u64 relu2(u64 a) {
    F2 v; v.u = a;
    v.f[0] = fmaxf(v.f[0], 0.0f);
    v.f[1] = fmaxf(v.f[1], 0.0f);
    return v.u;
}

// ---------------------------------------------------------------------------
// Kernel 1: pre_x = x @ W1[:128] (bz=0), pre_yb = y @ W1[128:] + b1 (bz=1),
// stored transposed [hid][n]. Also zeroes the global accumulators.
// grid (HID/64, NS/64, 2), block (16,16). 64x64 tile, 4x4 micro, f32x2 packed.
// ---------------------------------------------------------------------------
__global__ void gemm_pre_kernel(const float* __restrict__ x,
                                const float* __restrict__ y,
                                const float* __restrict__ W1,
                                const float* __restrict__ b1) {
    const int bz = blockIdx.z;
    const float* __restrict__ A = bz ? y : x;
    const float* __restrict__ W = W1 + (bz ? (XD * HID) : 0);
    float* __restrict__ outT = bz ? g_py_t : g_px_t;

    __shared__ float As[16][64];   // [k][n]
    __shared__ float Bs[16][64];   // [k][h]

    const int tx = threadIdx.x, ty = threadIdx.y;
    const int tid = ty * 16 + tx;
    const int n0 = blockIdx.y * 64;
    const int h0 = blockIdx.x * 64;

    if (blockIdx.x == 0 && blockIdx.y == 0 && bz == 0 && tid == 0) {
        g_sum_exp = 0.0f;
        g_sum_diag = 0.0f;
    }

    u64 acc[4][2];
#pragma unroll
    for (int a = 0; a < 4; a++) { acc[a][0] = 0ull; acc[a][1] = 0ull; }

    for (int kk = 0; kk < XD; kk += 16) {
        {
            int m  = tid >> 2;
            int k4 = (tid & 3) * 4;
            float4 v = *(const float4*)&A[(n0 + m) * XD + kk + k4];
            As[k4 + 0][m] = v.x;
            As[k4 + 1][m] = v.y;
            As[k4 + 2][m] = v.z;
            As[k4 + 3][m] = v.w;
        }
        {
#pragma unroll
            for (int t = 0; t < 4; t++) {
                int e = tid + t * 256;
                int h = e & 63;
                int k = e >> 6;
                Bs[k][h] = W[(kk + k) * HID + h0 + h];
            }
        }
        __syncthreads();

#pragma unroll
        for (int k = 0; k < 16; k++) {
            float4 av = *(const float4*)&As[k][ty * 4];
            ulonglong2 bv = *(const ulonglong2*)&Bs[k][tx * 4];
            float aa[4] = {av.x, av.y, av.z, av.w};
#pragma unroll
            for (int a = 0; a < 4; a++) {
                u64 ap = pack2(aa[a], aa[a]);
                acc[a][0] = fma2(ap, bv.x, acc[a][0]);
                acc[a][1] = fma2(ap, bv.y, acc[a][1]);
            }
        }
        __syncthreads();
    }

    // Store transposed: outT[h][n], float4 along n.
#pragma unroll
    for (int b = 0; b < 4; b++) {
        int h = h0 + tx * 4 + b;
        float bias = bz ? b1[h] : 0.0f;
        F2 p0, p1, p2, p3;
        p0.u = acc[0][b >> 1]; p1.u = acc[1][b >> 1];
        p2.u = acc[2][b >> 1]; p3.u = acc[3][b >> 1];
        int hl = b & 1;
        float4 v = make_float4(p0.f[hl] + bias, p1.f[hl] + bias,
                               p2.f[hl] + bias, p3.f[hl] + bias);
        *(float4*)&outT[h * NS + n0 + ty * 4] = v;
    }
}

// ---------------------------------------------------------------------------
// Kernel 2: fused pairwise T1 + exp-sum + diag-sum + (last block) finalize.
// grid (8, 32), block 128. Tile: 32 i x 128 j, 4x8 micro (j packed in f32x2).
// Thread t: i in {bi + (t>>4)*4 + 0..3}, j in {bj+4q..4q+3} u {bj+64+4q..+3},
// q = t&15.  Xs quarter-warp LDS.128 spans contiguous 128B -> conflict-free.
// ---------------------------------------------------------------------------
__global__ void __launch_bounds__(128)
pairwise_kernel(const float* __restrict__ W2, const float* __restrict__ b2,
                float* __restrict__ out) {
    __shared__ float Ys[32][32];     // [k][i_local]
    __shared__ float Xs[32][128];    // [k][j_local]
    __shared__ u64 w2p[HID];         // (w,w) pairs
    __shared__ float r1[4], r2[4];
    __shared__ bool is_last;

    const int t  = threadIdx.x;      // 0..127
    const int q  = t & 15;
    const int g  = t >> 4;           // 0..7
    const int bi = blockIdx.y * 32;
    const int bj = blockIdx.x * 128;

    // Pre-pack W2 as (w,w) pairs.
    for (int k = t; k < HID; k += 128) { float w = W2[k]; w2p[k] = pack2(w, w); }

    u64 acc[4][4];
#pragma unroll
    for (int a = 0; a < 4; a++)
#pragma unroll
        for (int p = 0; p < 4; p++) acc[a][p] = 0ull;

    for (int kk = 0; kk < HID; kk += 32) {
        // Ys: 32x32 floats = 256 float4; 2 per thread.
#pragma unroll
        for (int r = 0; r < 2; r++) {
            int f4 = t + r * 128;
            int k  = f4 >> 3;
            int c4 = (f4 & 7) * 4;
            *(float4*)&Ys[k][c4] = *(const float4*)&g_py_t[(kk + k) * NS + bi + c4];
        }
        // Xs: 32x128 floats = 1024 float4; 8 per thread.
#pragma unroll
        for (int r = 0; r < 8; r++) {
            int f4 = t + r * 128;
            int k  = f4 >> 5;
            int c4 = (f4 & 31) * 4;
            *(float4*)&Xs[k][c4] = *(const float4*)&g_px_t[(kk + k) * NS + bj + c4];
        }
        __syncthreads();

#pragma unroll 4
        for (int k = 0; k < 32; k++) {
            float4 yv = *(const float4*)&Ys[k][g * 4];
            ulonglong2 xa = *(const ulonglong2*)&Xs[k][q * 4];
            ulonglong2 xb = *(const ulonglong2*)&Xs[k][64 + q * 4];
            u64 wp = w2p[kk + k];
            u64 xp[4] = {xa.x, xa.y, xb.x, xb.y};
            float ya[4] = {yv.x, yv.y, yv.z, yv.w};
#pragma unroll
            for (int a = 0; a < 4; a++) {
                u64 yp = pack2(ya[a], ya[a]);
#pragma unroll
                for (int p = 0; p < 4; p++) {
                    u64 s = relu2(add2(yp, xp[p]));
                    acc[a][p] = fma2(s, wp, acc[a][p]);
                }
            }
        }
        __syncthreads();
    }

    const float c = b2[0] - 1.0f;
    float sexp = 0.0f, sdiag = 0.0f;

#pragma unroll
    for (int a = 0; a < 4; a++)
#pragma unroll
        for (int p = 0; p < 4; p++) {
            F2 v; v.u = acc[a][p];
            sexp += __expf(v.f[0] + c) + __expf(v.f[1] + c);
        }

    // Diagonal extraction: columns of pair p are base[p] + {0,1}.
    {
        int base[4] = {q * 4, q * 4 + 2, 64 + q * 4, 66 + q * 4};
#pragma unroll
        for (int a = 0; a < 4; a++) {
            int gi = bi + g * 4 + a;
            int jj = gi - bj;
            if (jj >= 0 && jj < 128) {
#pragma unroll
                for (int p = 0; p < 4; p++) {
                    if (jj == base[p] || jj == base[p] + 1) {
                        F2 v; v.u = acc[a][p];
                        sdiag += v.f[jj - base[p]] + c;
                    }
                }
            }
        }
    }

    // Block reduction: 4 warps.
    const int lane = t & 31, wid = t >> 5;
#pragma unroll
    for (int o = 16; o > 0; o >>= 1) {
        sexp  += __shfl_down_sync(0xFFFFFFFFu, sexp,  o);
        sdiag += __shfl_down_sync(0xFFFFFFFFu, sdiag, o);
    }
    if (lane == 0) { r1[wid] = sexp; r2[wid] = sdiag; }
    __syncthreads();
    if (t == 0) {
        float s1 = r1[0] + r1[1] + r1[2] + r1[3];
        float s2 = r2[0] + r2[1] + r2[2] + r2[3];
        atomicAdd(&g_sum_exp,  s1);
        atomicAdd(&g_sum_diag, s2);
        __threadfence();
        unsigned v = atomicAdd(&g_done, 1u);
        is_last = (v == gridDim.x * gridDim.y - 1);
    }
    __syncthreads();

    // Last block finalizes (replaces separate finalize kernel).
    if (is_last && t == 0) {
        g_done = 0;
        __threadfence();
        float n = (float)NS;
        out[0] = (g_sum_diag + n) / n - g_sum_exp / (n * n);
    }
}

// ---------------------------------------------------------------------------
extern "C" void kernel_launch(void* const* d_in, const int* in_sizes, int n_in,
                              void* d_out, int out_size) {
    const float* x  = (const float*)d_in[0];
    const float* y  = (const float*)d_in[1];
    const float* W1 = (const float*)d_in[2];
    const float* b1 = (const float*)d_in[3];
    const float* W2 = (const float*)d_in[4];
    const float* b2 = (const float*)d_in[5];
    float* out = (float*)d_out;

    dim3 blk1(16, 16);
    dim3 g1(HID / 64, NS / 64, 2);
    gemm_pre_kernel<<<g1, blk1>>>(x, y, W1, b1);

    dim3 g2(NS / 128, NS / 32);
    pairwise_kernel<<<g2, 128>>>(W2, b2, out);
}